// round 5
// baseline (speedup 1.0000x reference)
#include <cuda_runtime.h>
#include <cstdint>

// Problem constants
#define Bq 2
#define Sq 2048
#define Eq 768
#define Hq 12
#define Gq 4
#define Dq 64
#define Tq 512   // Sq / Gq

#define EEc  ((size_t)Eq * Eq)
#define BTEc ((size_t)Bq * Tq * Eq)
#define BSEc ((size_t)Bq * Sq * Eq)

// ---------------------------------------------------------------------------
// Scratch (device globals)
// ---------------------------------------------------------------------------
__device__ float g_wc[12 * EEc];     // composed weights: [q g0..3 | k g0..3 | v g0..3]
__device__ float g_bc[12 * Eq];      // composed biases
__device__ float g_qi [Gq*Bq*Tq*Eq];
__device__ float g_ki [(size_t)Gq*Bq*Sq*Eq];
__device__ float g_vi [(size_t)Gq*Bq*Sq*Eq];
__device__ float g_ctx[Gq*Bq*Tq*Eq];

// ---------------------------------------------------------------------------
// tf32 helpers
// ---------------------------------------------------------------------------
__device__ __forceinline__ float f2tf32(float x) {
    uint32_t r;
    asm("cvt.rna.tf32.f32 %0, %1;" : "=r"(r) : "f"(x));
    return __uint_as_float(r);
}
__device__ __forceinline__ float4 f2tf32_4(float4 v) {
    return make_float4(f2tf32(v.x), f2tf32(v.y), f2tf32(v.z), f2tf32(v.w));
}
__device__ __forceinline__ void mma_tf32(float (&d)[4], const float a[4], const float b[2]) {
    asm volatile(
        "mma.sync.aligned.m16n8k8.row.col.f32.tf32.tf32.f32 "
        "{%0,%1,%2,%3}, {%4,%5,%6,%7}, {%8,%9}, {%0,%1,%2,%3};\n"
        : "+f"(d[0]), "+f"(d[1]), "+f"(d[2]), "+f"(d[3])
        : "r"(__float_as_uint(a[0])), "r"(__float_as_uint(a[1])),
          "r"(__float_as_uint(a[2])), "r"(__float_as_uint(a[3])),
          "r"(__float_as_uint(b[0])), "r"(__float_as_uint(b[1])));
}

// ---------------------------------------------------------------------------
// Unified tf32 GEMM, double-buffered smem, 128 thr, tile 128m x 64n.
// C[m][n] = sum_k A[m][k] * W[n][k] (+ bias[n]); K = N = 768.
// MODE 0: weight compose  Wc[z] = Win[sel][g] @ Wouter[sel]   (W read transposed)
// MODE 1: projections     z<4: ki = key@Wc_k ; z<8: vi = value@Wc_v ;
//                         z>=8: qi = gather_g(query)@Wc_q   (y-guarded, amap)
// MODE 2: output          out = scatter_g(ctx[z] @ Wout[z].T + bout[z])
// ---------------------------------------------------------------------------
#define GS 20

template<int MODE>
__global__ __launch_bounds__(128)
void gemm_k(const float* __restrict__ P0, const float* __restrict__ P1,
            const float* __restrict__ P2, const float* __restrict__ P3,
            const float* __restrict__ P4, const float* __restrict__ P5,
            float* __restrict__ O0, float* __restrict__ O1, float* __restrict__ O2)
{
    __shared__ float As[2][128 * GS];
    __shared__ float Ws[2][64 * GS];

    const int z = blockIdx.z;
    const int sel = z >> 2, g = z & 3;

    const float* Ab; const float* Wb; const float* bb = nullptr; float* Cb;
    bool amap = false, cmap = false;
    if (MODE == 0) {
        const float* Wins[3] = {P0, P1, P2};
        const float* Wos[3]  = {P3, P4, P5};
        Ab = Wins[sel] + (size_t)g * EEc;
        Wb = Wos[sel];
        Cb = O0 + (size_t)z * EEc;
    } else if (MODE == 1) {
        if (sel == 2 && blockIdx.y >= 8) return;
        if (sel == 0)      { Ab = P1; Wb = P3 + (size_t)(4+g)*EEc; bb = P4 + (4+g)*Eq; Cb = O0 + (size_t)g*BSEc; }
        else if (sel == 1) { Ab = P2; Wb = P3 + (size_t)(8+g)*EEc; bb = P4 + (8+g)*Eq; Cb = O1 + (size_t)g*BSEc; }
        else               { Ab = P0; Wb = P3 + (size_t)g*EEc;     bb = P4 + g*Eq;     Cb = O2 + (size_t)g*BTEc; amap = true; }
    } else {
        Ab = P0 + (size_t)z * BTEc;
        Wb = P1 + (size_t)z * EEc;
        bb = P2 + z * Eq;
        Cb = O0; cmap = true;
    }

    const int m0 = blockIdx.y * 128;
    const int n0 = blockIdx.x * 64;
    const int tid  = threadIdx.x;
    const int wid  = tid >> 5;
    const int lane = tid & 31;
    const int gid  = lane >> 2;
    const int t4   = lane & 3;
    const int wm   = (wid & 1) * 64;
    const int wn   = (wid >> 1) * 32;

    float acc[4][4][4];
    #pragma unroll
    for (int a = 0; a < 4; a++)
        #pragma unroll
        for (int b = 0; b < 4; b++)
            #pragma unroll
            for (int c = 0; c < 4; c++) acc[a][b][c] = 0.f;

    float4 pa[4], pw[2];

    auto loadA = [&](int k0) {
        #pragma unroll
        for (int p = 0; p < 4; p++) {
            int idx = tid + p * 128;
            int row = m0 + (idx >> 2);
            int q = (idx & 3) * 4;
            size_t gr;
            if (amap) gr = (size_t)(row >> 9) * Sq + (size_t)(row & 511) * Gq + g;
            else      gr = (size_t)row;
            pa[p] = *(const float4*)&Ab[gr * Eq + k0 + q];
        }
    };
    auto loadW = [&](int k0) {
        if (MODE != 0) {
            #pragma unroll
            for (int p = 0; p < 2; p++) {
                int idx = tid + p * 128;
                int row = n0 + (idx >> 2);
                int q = (idx & 3) * 4;
                pw[p] = *(const float4*)&Wb[(size_t)row * Eq + k0 + q];
            }
        } else {
            // transposed read: e = k within chunk, j*4 = n within tile
            #pragma unroll
            for (int p = 0; p < 2; p++) {
                int idx = tid + p * 128;
                int e  = idx & 15;
                int jq = (idx >> 4) * 4;
                pw[p] = *(const float4*)&Wb[(size_t)(k0 + e) * Eq + n0 + jq];
            }
        }
    };
    auto storeT = [&](int buf) {
        #pragma unroll
        for (int p = 0; p < 4; p++) {
            int idx = tid + p * 128;
            int row = idx >> 2;
            int q = (idx & 3) * 4;
            *(float4*)&As[buf][row * GS + q] = f2tf32_4(pa[p]);
        }
        if (MODE != 0) {
            #pragma unroll
            for (int p = 0; p < 2; p++) {
                int idx = tid + p * 128;
                int row = idx >> 2;
                int q = (idx & 3) * 4;
                *(float4*)&Ws[buf][row * GS + q] = f2tf32_4(pw[p]);
            }
        } else {
            // conflict-free scatter: banks (20i + e) and (16 + 20i + e)
            #pragma unroll
            for (int p = 0; p < 2; p++) {
                int idx = tid + p * 128;
                int e  = idx & 15;
                int jq = (idx >> 4) * 4;
                float4 v = f2tf32_4(pw[p]);
                Ws[buf][(jq + 0) * GS + e] = v.x;
                Ws[buf][(jq + 1) * GS + e] = v.y;
                Ws[buf][(jq + 2) * GS + e] = v.z;
                Ws[buf][(jq + 3) * GS + e] = v.w;
            }
        }
    };
    auto compute = [&](int buf) {
        #pragma unroll
        for (int kk = 0; kk < 2; kk++) {
            float afr[4][4];
            #pragma unroll
            for (int mt = 0; mt < 4; mt++) {
                int r = wm + mt * 16 + gid;
                int c = kk * 8 + t4;
                afr[mt][0] = As[buf][r * GS + c];
                afr[mt][1] = As[buf][(r + 8) * GS + c];
                afr[mt][2] = As[buf][r * GS + c + 4];
                afr[mt][3] = As[buf][(r + 8) * GS + c + 4];
            }
            float bfr[4][2];
            #pragma unroll
            for (int nt = 0; nt < 4; nt++) {
                int r = wn + nt * 8 + gid;
                int c = kk * 8 + t4;
                bfr[nt][0] = Ws[buf][r * GS + c];
                bfr[nt][1] = Ws[buf][r * GS + c + 4];
            }
            #pragma unroll
            for (int mt = 0; mt < 4; mt++)
                #pragma unroll
                for (int nt = 0; nt < 4; nt++)
                    mma_tf32(acc[mt][nt], afr[mt], bfr[nt]);
        }
    };

    loadA(0); loadW(0);
    storeT(0);
    __syncthreads();

    int buf = 0;
    const int NCH = Eq / 16;   // 48
    for (int c = 0; c < NCH; c++) {
        if (c + 1 < NCH) { loadA((c + 1) * 16); loadW((c + 1) * 16); }
        compute(buf);
        if (c + 1 < NCH) storeT(1 - buf);
        __syncthreads();
        buf ^= 1;
    }

    #pragma unroll
    for (int mt = 0; mt < 4; mt++) {
        int m = m0 + wm + mt * 16 + gid;
        size_t r0, r1;
        if (cmap) {
            r0 = (size_t)(m >> 9) * Sq + (size_t)(m & 511) * Gq + g;
            r1 = (size_t)((m + 8) >> 9) * Sq + (size_t)((m + 8) & 511) * Gq + g;
        } else {
            r0 = (size_t)m; r1 = (size_t)(m + 8);
        }
        #pragma unroll
        for (int nt = 0; nt < 4; nt++) {
            int n = n0 + wn + nt * 8 + 2 * t4;
            float b0 = 0.f, b1 = 0.f;
            if (MODE != 0) { b0 = bb[n]; b1 = bb[n + 1]; }
            *(float2*)&Cb[r0 * Eq + n] = make_float2(acc[mt][nt][0] + b0, acc[mt][nt][1] + b1);
            *(float2*)&Cb[r1 * Eq + n] = make_float2(acc[mt][nt][2] + b0, acc[mt][nt][3] + b1);
        }
    }
}

// ---------------------------------------------------------------------------
// Fused bias compose: bc[y][f] = dot(Win[sel][g][f][:], b_outer[sel]) + b_in[sel][g][f]
// grid (Eq/8, 12), block 256: one warp per output row.
// ---------------------------------------------------------------------------
__global__ void biascomp_all(const float* __restrict__ Wq_in, const float* __restrict__ Wk_in,
                             const float* __restrict__ Wv_in,
                             const float* __restrict__ bqg, const float* __restrict__ bk,
                             const float* __restrict__ bv,
                             const float* __restrict__ bq_in, const float* __restrict__ bk_in,
                             const float* __restrict__ bv_in,
                             float* __restrict__ bc)
{
    int y = blockIdx.y;          // 0..11
    int sel = y >> 2, g = y & 3;
    const float* Win = (sel == 0 ? Wq_in : sel == 1 ? Wk_in : Wv_in) + (size_t)g * EEc;
    const float* bo  = (sel == 0 ? bqg : sel == 1 ? bk : bv);
    const float* bi  = (sel == 0 ? bq_in : sel == 1 ? bk_in : bv_in) + g * Eq;
    int f = blockIdx.x * 8 + (threadIdx.x >> 5);
    int lane = threadIdx.x & 31;
    const float* wr = Win + (size_t)f * Eq;
    float s = 0.f;
    for (int j = lane * 4; j < Eq; j += 128) {
        float4 w = *(const float4*)&wr[j];
        float4 b = *(const float4*)&bo[j];
        s += w.x*b.x + w.y*b.y + w.z*b.z + w.w*b.w;
    }
    #pragma unroll
    for (int o = 16; o; o >>= 1) s += __shfl_xor_sync(0xffffffffu, s, o);
    if (lane == 0) bc[(size_t)y * Eq + f] = s + bi[f];
}

// ---------------------------------------------------------------------------
// Flash attention, tf32 MMA, 64-key chunks.
// grid (T/64, H, G*B), block 128 (4 warps, 16 q-rows each). Dynamic smem.
// ---------------------------------------------------------------------------
#define KSTR 68
#define VSTR 72
#define QSTR 68
#define FLASH_SMEM ((64*KSTR + 64*VSTR + 64*QSTR) * 4)

__global__ __launch_bounds__(128)
void flash_tf32_kernel(const float* __restrict__ qi,
                       const float* __restrict__ ki,
                       const float* __restrict__ vi,
                       float* __restrict__ ctx)
{
    extern __shared__ float sm[];
    float* Ks  = sm;
    float* Vs  = Ks + 64 * KSTR;
    float* QPs = Vs + 64 * VSTR;

    const int zz = blockIdx.z;
    const int h  = blockIdx.y;
    const int t0 = blockIdx.x * 64;
    const size_t qbase = ((size_t)zz * Tq + t0) * Eq + (size_t)h * Dq;
    const size_t kbase = (size_t)zz * Sq * Eq + (size_t)h * Dq;

    const int tid  = threadIdx.x;
    const int wid  = tid >> 5;
    const int lane = tid & 31;
    const int gid  = lane >> 2;
    const int t4   = lane & 3;
    const int wrow = wid * 16;

    #pragma unroll
    for (int i = 0; i < 8; i++) {
        int idx = tid + i * 128;
        int row = idx >> 4;
        int c4  = idx & 15;
        float4 v = *(const float4*)&qi[qbase + (size_t)row * Eq + c4 * 4];
        *(float4*)&QPs[row * QSTR + c4 * 4] = f2tf32_4(v);
    }
    __syncthreads();

    float Aq[8][4];
    #pragma unroll
    for (int kk = 0; kk < 8; kk++) {
        int r = wrow + gid;
        int c = kk * 8 + t4;
        Aq[kk][0] = QPs[r * QSTR + c];
        Aq[kk][1] = QPs[(r + 8) * QSTR + c];
        Aq[kk][2] = QPs[r * QSTR + c + 4];
        Aq[kk][3] = QPs[(r + 8) * QSTR + c + 4];
    }

    float out[8][4];
    #pragma unroll
    for (int j = 0; j < 8; j++)
        #pragma unroll
        for (int c = 0; c < 4; c++) out[j][c] = 0.f;
    float mrow[2] = {-1e30f, -1e30f};
    float lrow[2] = {0.f, 0.f};
    const float kappa = 0.125f * 1.44269504088896340736f;

    for (int s0 = 0; s0 < Sq; s0 += 64) {
        __syncthreads();
        #pragma unroll
        for (int i = 0; i < 8; i++) {
            int idx = tid + i * 128;
            int row = idx >> 4;
            int c4  = idx & 15;
            size_t go = kbase + (size_t)(s0 + row) * Eq + c4 * 4;
            float4 kv = *(const float4*)&ki[go];
            float4 vv = *(const float4*)&vi[go];
            *(float4*)&Ks[row * KSTR + c4 * 4] = f2tf32_4(kv);
            *(float4*)&Vs[row * VSTR + c4 * 4] = f2tf32_4(vv);
        }
        __syncthreads();

        float sc[8][4];
        #pragma unroll
        for (int j = 0; j < 8; j++)
            #pragma unroll
            for (int c = 0; c < 4; c++) sc[j][c] = 0.f;
        #pragma unroll
        for (int kk = 0; kk < 8; kk++) {
            #pragma unroll
            for (int j = 0; j < 8; j++) {
                float bfr[2];
                int key = j * 8 + gid;
                int d   = kk * 8 + t4;
                bfr[0] = Ks[key * KSTR + d];
                bfr[1] = Ks[key * KSTR + d + 4];
                mma_tf32(sc[j], Aq[kk], bfr);
            }
        }

        #pragma unroll
        for (int j = 0; j < 8; j++)
            #pragma unroll
            for (int c = 0; c < 4; c++) sc[j][c] *= kappa;

        #pragma unroll
        for (int r = 0; r < 2; r++) {
            float mx = -1e30f;
            #pragma unroll
            for (int j = 0; j < 8; j++)
                mx = fmaxf(mx, fmaxf(sc[j][2*r], sc[j][2*r + 1]));
            mx = fmaxf(mx, __shfl_xor_sync(0xffffffffu, mx, 1));
            mx = fmaxf(mx, __shfl_xor_sync(0xffffffffu, mx, 2));
            float mn = fmaxf(mrow[r], mx);
            float corr = exp2f(mrow[r] - mn);
            mrow[r] = mn;
            float rs = 0.f;
            #pragma unroll
            for (int j = 0; j < 8; j++) {
                float p0 = exp2f(sc[j][2*r]     - mn);
                float p1 = exp2f(sc[j][2*r + 1] - mn);
                sc[j][2*r]     = p0;
                sc[j][2*r + 1] = p1;
                rs += p0 + p1;
            }
            rs += __shfl_xor_sync(0xffffffffu, rs, 1);
            rs += __shfl_xor_sync(0xffffffffu, rs, 2);
            lrow[r] = lrow[r] * corr + rs;
            #pragma unroll
            for (int j = 0; j < 8; j++) {
                out[j][2*r]     *= corr;
                out[j][2*r + 1] *= corr;
            }
        }

        #pragma unroll
        for (int j = 0; j < 8; j++) {
            int col = j * 8 + 2 * t4;
            *(float2*)&QPs[(wrow + gid) * QSTR + col] =
                make_float2(f2tf32(sc[j][0]), f2tf32(sc[j][1]));
            *(float2*)&QPs[(wrow + gid + 8) * QSTR + col] =
                make_float2(f2tf32(sc[j][2]), f2tf32(sc[j][3]));
        }
        __syncwarp();

        #pragma unroll
        for (int kk = 0; kk < 8; kk++) {
            float afr[4];
            int r = wrow + gid;
            int c = kk * 8 + t4;
            afr[0] = QPs[r * QSTR + c];
            afr[1] = QPs[(r + 8) * QSTR + c];
            afr[2] = QPs[r * QSTR + c + 4];
            afr[3] = QPs[(r + 8) * QSTR + c + 4];
            #pragma unroll
            for (int j = 0; j < 8; j++) {
                float bfr[2];
                int key = kk * 8 + t4;
                int d   = j * 8 + gid;
                bfr[0] = Vs[key * VSTR + d];
                bfr[1] = Vs[(key + 4) * VSTR + d];
                mma_tf32(out[j], afr, bfr);
            }
        }
    }

    float inv0 = 1.0f / lrow[0];
    float inv1 = 1.0f / lrow[1];
    int r0 = wrow + gid;
    #pragma unroll
    for (int j = 0; j < 8; j++) {
        int col = j * 8 + 2 * t4;
        *(float2*)&ctx[qbase + (size_t)r0 * Eq + col] =
            make_float2(out[j][0] * inv0, out[j][1] * inv0);
        *(float2*)&ctx[qbase + (size_t)(r0 + 8) * Eq + col] =
            make_float2(out[j][2] * inv1, out[j][3] * inv1);
    }
}

// ---------------------------------------------------------------------------
// Launch
// ---------------------------------------------------------------------------
extern "C" void kernel_launch(void* const* d_in, const int* in_sizes, int n_in,
                              void* d_out, int out_size)
{
    const float* query = (const float*)d_in[0];
    const float* key_  = (const float*)d_in[1];
    const float* value = (const float*)d_in[2];
    const float* Wqg   = (const float*)d_in[3];
    const float* bqg   = (const float*)d_in[4];
    const float* Wk    = (const float*)d_in[5];
    const float* bk    = (const float*)d_in[6];
    const float* Wv    = (const float*)d_in[7];
    const float* bv    = (const float*)d_in[8];
    const float* Wq_in = (const float*)d_in[9];
    const float* bq_in = (const float*)d_in[10];
    const float* Wk_in = (const float*)d_in[11];
    const float* bk_in = (const float*)d_in[12];
    const float* Wv_in = (const float*)d_in[13];
    const float* bv_in = (const float*)d_in[14];
    const float* Wout  = (const float*)d_in[15];
    const float* bout  = (const float*)d_in[16];
    float* out = (float*)d_out;

    float *wc, *bc, *qiP, *kiP, *viP, *ctx;
    cudaGetSymbolAddress((void**)&wc,  g_wc);
    cudaGetSymbolAddress((void**)&bc,  g_bc);
    cudaGetSymbolAddress((void**)&qiP, g_qi);
    cudaGetSymbolAddress((void**)&kiP, g_ki);
    cudaGetSymbolAddress((void**)&viP, g_vi);
    cudaGetSymbolAddress((void**)&ctx, g_ctx);

    cudaFuncSetAttribute(flash_tf32_kernel,
                         cudaFuncAttributeMaxDynamicSharedMemorySize, FLASH_SMEM);

    // 1) Fused bias compose (12 rows-of-768 jobs in one launch)
    biascomp_all<<<dim3(Eq / 8, 12), 256>>>(Wq_in, Wk_in, Wv_in,
                                            bqg, bk, bv,
                                            bq_in, bk_in, bv_in, bc);

    // 2) Fused weight compose: wc[z] = Win[sel][g] @ Wouter[sel]
    gemm_k<0><<<dim3(Eq / 64, Eq / 128, 12), 128>>>(
        Wq_in, Wk_in, Wv_in, Wqg, Wk, Wv, wc, nullptr, nullptr);

    // 3) Fused projections: ki, vi, qi in one launch
    gemm_k<1><<<dim3(Eq / 64, (Bq * Sq) / 128, 12), 128>>>(
        query, key_, value, wc, bc, nullptr, kiP, viP, qiP);

    // 4) Attention
    flash_tf32_kernel<<<dim3(Tq / 64, Hq, Bq * Gq), 128, FLASH_SMEM>>>(qiP, kiP, viP, ctx);

    // 5) Output projection + scatter
    gemm_k<2><<<dim3(Eq / 64, (Bq * Tq) / 128, Gq), 128>>>(
        ctx, Wout, bout, nullptr, nullptr, nullptr, out, nullptr, nullptr);
}

// round 9
// speedup vs baseline: 1.7018x; 1.7018x over previous
#include <cuda_runtime.h>
#include <cuda_bf16.h>
#include <cstdint>

// Problem constants
#define Bq 2
#define Sq 2048
#define Eq 768
#define Hq 12
#define Gq 4
#define Dq 64
#define Tq 512   // Sq / Gq

#define EEc  ((size_t)Eq * Eq)
#define BTEc ((size_t)Bq * Tq * Eq)
#define BSEc ((size_t)Bq * Sq * Eq)

// ---------------------------------------------------------------------------
// Scratch (device globals)
// ---------------------------------------------------------------------------
__device__ float g_wc[12 * EEc];     // composed weights [q g0..3 | k g0..3 | v g0..3]
__device__ float g_bc[12 * Eq];      // composed biases
__device__ __nv_bfloat16 g_qib[(size_t)Gq*Bq*Tq*Eq];   // [g][b*T+t][f] bf16
__device__ __nv_bfloat16 g_kib[(size_t)Gq*Bq*Sq*Eq];   // [g][b*S+s][f] bf16
__device__ float g_vi [(size_t)Gq*Bq*Sq*Eq];           // [g][b*S+s][f] fp32
__device__ float g_ctx[(size_t)Gq*Bq*Tq*Eq];           // [g][b*T+t][f] fp32

// ---------------------------------------------------------------------------
// helpers
// ---------------------------------------------------------------------------
__device__ __forceinline__ float f2tf32(float x) {
    uint32_t r;
    asm("cvt.rna.tf32.f32 %0, %1;" : "=r"(r) : "f"(x));
    return __uint_as_float(r);
}
__device__ __forceinline__ float4 f2tf32_4(float4 v) {
    return make_float4(f2tf32(v.x), f2tf32(v.y), f2tf32(v.z), f2tf32(v.w));
}
__device__ __forceinline__ void mma_tf32(float (&d)[4], const float a[4], const float b[2]) {
    asm volatile(
        "mma.sync.aligned.m16n8k8.row.col.f32.tf32.tf32.f32 "
        "{%0,%1,%2,%3}, {%4,%5,%6,%7}, {%8,%9}, {%0,%1,%2,%3};\n"
        : "+f"(d[0]), "+f"(d[1]), "+f"(d[2]), "+f"(d[3])
        : "r"(__float_as_uint(a[0])), "r"(__float_as_uint(a[1])),
          "r"(__float_as_uint(a[2])), "r"(__float_as_uint(a[3])),
          "r"(__float_as_uint(b[0])), "r"(__float_as_uint(b[1])));
}
__device__ __forceinline__ void mma_bf16(float (&d)[4], const uint32_t a[4], const uint32_t b[2]) {
    asm volatile(
        "mma.sync.aligned.m16n8k16.row.col.f32.bf16.bf16.f32 "
        "{%0,%1,%2,%3}, {%4,%5,%6,%7}, {%8,%9}, {%0,%1,%2,%3};\n"
        : "+f"(d[0]), "+f"(d[1]), "+f"(d[2]), "+f"(d[3])
        : "r"(a[0]), "r"(a[1]), "r"(a[2]), "r"(a[3]),
          "r"(b[0]), "r"(b[1]));
}
__device__ __forceinline__ uint32_t packbf(float lo, float hi) {
    uint32_t r;
    asm("cvt.rn.bf16x2.f32 %0, %1, %2;" : "=r"(r) : "f"(hi), "f"(lo));
    return r;
}

// ---------------------------------------------------------------------------
// Unified tf32 GEMM (single-buffer smem, reg prefetch), 128 thr, 128m x 64n.
// MODE 0: weight compose wc[z] = Win[sel][g] @ Wouter[sel]  (W read [k][n])
// MODE 1: projections: sel0 ki(bf16) = key@Wc_k ; sel1 vi(f32) = value@Wc_v ;
//                      sel2 qi(bf16) = gather_g(query)@Wc_q  (y<8)
// MODE 2: output out = scatter_g(ctx[z] @ Wout[z].T + bout[z])
// ---------------------------------------------------------------------------
#define GS 20
#define WKN 72

template<int MODE>
__global__ __launch_bounds__(128)
void gemm_k(const float* __restrict__ P0, const float* __restrict__ P1,
            const float* __restrict__ P2, const float* __restrict__ P3,
            const float* __restrict__ P4, const float* __restrict__ P5,
            float* __restrict__ O0, float* __restrict__ O1, float* __restrict__ O2)
{
    __shared__ float As[128 * GS];   // 2560 floats
    __shared__ float Ws[64 * GS];    // 1280 floats (covers MODE0's 16*72=1152 too)

    const int z = blockIdx.z;
    const int sel = z >> 2, g = z & 3;

    const float* Ab; const float* Wb; const float* bb = nullptr; float* Cb = nullptr;
    bool amap = false, cmap = false, bfout = false;
    if (MODE == 0) {
        Ab = (sel == 0 ? P0 : sel == 1 ? P1 : P2) + (size_t)g * EEc;
        Wb = (sel == 0 ? P3 : sel == 1 ? P4 : P5);
        Cb = O0 + (size_t)z * EEc;
    } else if (MODE == 1) {
        if (sel == 2 && blockIdx.y >= 8) return;
        if (sel == 0)      { Ab = P1; Wb = P3 + (size_t)(4+g)*EEc; bb = P4 + (4+g)*Eq; Cb = O0; bfout = true; }
        else if (sel == 1) { Ab = P2; Wb = P3 + (size_t)(8+g)*EEc; bb = P4 + (8+g)*Eq; Cb = O1 + (size_t)g*BSEc; }
        else               { Ab = P0; Wb = P3 + (size_t)g*EEc;     bb = P4 + g*Eq;     Cb = O2; bfout = true; amap = true; }
    } else {
        Ab = P0 + (size_t)z * BTEc;
        Wb = P1 + (size_t)z * EEc;
        bb = P2 + z * Eq;
        Cb = O0; cmap = true;
    }
    __nv_bfloat16* Cb16 = nullptr;
    if (MODE == 1 && bfout) {
        Cb16 = (sel == 0) ? ((__nv_bfloat16*)O0 + (size_t)g * BSEc)
                          : ((__nv_bfloat16*)O2 + (size_t)g * BTEc);
    }

    const int m0 = blockIdx.y * 128;
    const int n0 = blockIdx.x * 64;
    const int tid  = threadIdx.x;
    const int wid  = tid >> 5;
    const int lane = tid & 31;
    const int gid  = lane >> 2;
    const int t4   = lane & 3;
    const int wm   = (wid & 1) * 64;
    const int wn   = (wid >> 1) * 32;

    float acc[4][4][4];
    #pragma unroll
    for (int a = 0; a < 4; a++)
        #pragma unroll
        for (int b = 0; b < 4; b++)
            #pragma unroll
            for (int c = 0; c < 4; c++) acc[a][b][c] = 0.f;

    float4 pa[4], pw[2];

    auto loadA = [&](int k0) {
        #pragma unroll
        for (int p = 0; p < 4; p++) {
            int idx = tid + p * 128;
            int row = m0 + (idx >> 2);
            int q = (idx & 3) * 4;
            size_t gr;
            if (amap) gr = (size_t)(row >> 9) * Sq + (size_t)(row & 511) * Gq + g;
            else      gr = (size_t)row;
            pa[p] = *(const float4*)&Ab[gr * Eq + k0 + q];
        }
    };
    auto loadW = [&](int k0) {
        if (MODE != 0) {
            #pragma unroll
            for (int p = 0; p < 2; p++) {
                int idx = tid + p * 128;
                int row = n0 + (idx >> 2);
                int q = (idx & 3) * 4;
                pw[p] = *(const float4*)&Wb[(size_t)row * Eq + k0 + q];
            }
        } else {
            #pragma unroll
            for (int p = 0; p < 2; p++) {
                int idx = tid + p * 128;
                int e  = idx >> 4;
                int jq = (idx & 15) * 4;
                pw[p] = *(const float4*)&Wb[(size_t)(k0 + e) * Eq + n0 + jq];
            }
        }
    };
    auto storeT = [&]() {
        #pragma unroll
        for (int p = 0; p < 4; p++) {
            int idx = tid + p * 128;
            int row = idx >> 2;
            int q = (idx & 3) * 4;
            *(float4*)&As[row * GS + q] = f2tf32_4(pa[p]);
        }
        if (MODE != 0) {
            #pragma unroll
            for (int p = 0; p < 2; p++) {
                int idx = tid + p * 128;
                int row = idx >> 2;
                int q = (idx & 3) * 4;
                *(float4*)&Ws[row * GS + q] = f2tf32_4(pw[p]);
            }
        } else {
            #pragma unroll
            for (int p = 0; p < 2; p++) {
                int idx = tid + p * 128;
                int e  = idx >> 4;
                int jq = (idx & 15) * 4;
                *(float4*)&Ws[e * WKN + jq] = f2tf32_4(pw[p]);
            }
        }
    };

    loadA(0); loadW(0);

    for (int k0 = 0; k0 < Eq; k0 += 16) {
        storeT();
        __syncthreads();
        if (k0 + 16 < Eq) { loadA(k0 + 16); loadW(k0 + 16); }

        #pragma unroll
        for (int kk = 0; kk < 2; kk++) {
            float afr[4][4];
            #pragma unroll
            for (int mt = 0; mt < 4; mt++) {
                int r = wm + mt * 16 + gid;
                int c = kk * 8 + t4;
                afr[mt][0] = As[r * GS + c];
                afr[mt][1] = As[(r + 8) * GS + c];
                afr[mt][2] = As[r * GS + c + 4];
                afr[mt][3] = As[(r + 8) * GS + c + 4];
            }
            float bfr[4][2];
            #pragma unroll
            for (int nt = 0; nt < 4; nt++) {
                int r = wn + nt * 8 + gid;
                int c = kk * 8 + t4;
                if (MODE == 0) {
                    bfr[nt][0] = Ws[c * WKN + r];
                    bfr[nt][1] = Ws[(c + 4) * WKN + r];
                } else {
                    bfr[nt][0] = Ws[r * GS + c];
                    bfr[nt][1] = Ws[r * GS + c + 4];
                }
            }
            #pragma unroll
            for (int mt = 0; mt < 4; mt++)
                #pragma unroll
                for (int nt = 0; nt < 4; nt++)
                    mma_tf32(acc[mt][nt], afr[mt], bfr[nt]);
        }
        __syncthreads();
    }

    #pragma unroll
    for (int mt = 0; mt < 4; mt++) {
        int m  = m0 + wm + mt * 16 + gid;
        int m2 = m + 8;
        size_t r0, r1;
        if (cmap) {
            r0 = (size_t)(m  >> 9) * Sq + (size_t)(m  & 511) * Gq + g;
            r1 = (size_t)(m2 >> 9) * Sq + (size_t)(m2 & 511) * Gq + g;
        } else { r0 = (size_t)m; r1 = (size_t)m2; }
        #pragma unroll
        for (int nt = 0; nt < 4; nt++) {
            int n = n0 + wn + nt * 8 + 2 * t4;
            float b0 = 0.f, b1 = 0.f;
            if (MODE != 0) { b0 = bb[n]; b1 = bb[n + 1]; }
            if (MODE == 1 && bfout) {
                *(uint32_t*)&Cb16[r0 * Eq + n] = packbf(acc[mt][nt][0] + b0, acc[mt][nt][1] + b1);
                *(uint32_t*)&Cb16[r1 * Eq + n] = packbf(acc[mt][nt][2] + b0, acc[mt][nt][3] + b1);
            } else {
                *(float2*)&Cb[r0 * Eq + n] = make_float2(acc[mt][nt][0] + b0, acc[mt][nt][1] + b1);
                *(float2*)&Cb[r1 * Eq + n] = make_float2(acc[mt][nt][2] + b0, acc[mt][nt][3] + b1);
            }
        }
    }
}

// ---------------------------------------------------------------------------
// Fused bias compose
// ---------------------------------------------------------------------------
__global__ void biascomp_all(const float* __restrict__ Wq_in, const float* __restrict__ Wk_in,
                             const float* __restrict__ Wv_in,
                             const float* __restrict__ bqg, const float* __restrict__ bk,
                             const float* __restrict__ bv,
                             const float* __restrict__ bq_in, const float* __restrict__ bk_in,
                             const float* __restrict__ bv_in,
                             float* __restrict__ bc)
{
    int y = blockIdx.y;
    int sel = y >> 2, g = y & 3;
    const float* Win = (sel == 0 ? Wq_in : sel == 1 ? Wk_in : Wv_in) + (size_t)g * EEc;
    const float* bo  = (sel == 0 ? bqg : sel == 1 ? bk : bv);
    const float* bi  = (sel == 0 ? bq_in : sel == 1 ? bk_in : bv_in) + g * Eq;
    int f = blockIdx.x * 8 + (threadIdx.x >> 5);
    int lane = threadIdx.x & 31;
    const float* wr = Win + (size_t)f * Eq;
    float s = 0.f;
    for (int j = lane * 4; j < Eq; j += 128) {
        float4 w = *(const float4*)&wr[j];
        float4 b = *(const float4*)&bo[j];
        s += w.x*b.x + w.y*b.y + w.z*b.z + w.w*b.w;
    }
    #pragma unroll
    for (int o = 16; o; o >>= 1) s += __shfl_xor_sync(0xffffffffu, s, o);
    if (lane == 0) bc[(size_t)y * Eq + f] = s + bi[f];
}

// ---------------------------------------------------------------------------
// Flash attention, mixed precision:
//   QK: bf16 MMA (m16n8k16), Q/K bf16 smem (stride 72 bf16)
//   softmax fp32; P staged tf32-f32 at STRIDE 68 (the R7 bug was stride 20)
//   PV: tf32 MMA (m16n8k8), V f32 smem (stride 72)
// grid (T/64, H, G*B), block 128 (4 warps x 16 q-rows), 64-key chunks.
// ---------------------------------------------------------------------------
#define KSB 72   // K smem stride (bf16)
#define VSF 72   // V smem stride (f32)
#define QSB 72   // Q staging stride (bf16)
#define PSF 68   // P smem stride (f32): r*68+c -> banks 4*gid+t4, conflict-free

__global__ __launch_bounds__(128)
void flash_mixed_kernel(const __nv_bfloat16* __restrict__ qi,
                        const __nv_bfloat16* __restrict__ ki,
                        const float* __restrict__ vi,
                        float* __restrict__ ctx)
{
    __shared__ __align__(16) __nv_bfloat16 Ks[64 * KSB];        // 9216 B
    __shared__ __align__(16) float         Vs[64 * VSF];        // 18432 B
    __shared__ __align__(16) unsigned char QPbuf[64 * PSF * 4]; // 17408 B (Q bf16 / P f32)
    __nv_bfloat16* Qs = (__nv_bfloat16*)QPbuf;   // stride QSB=72 bf16: 9216 B used
    float*         Ps = (float*)QPbuf;           // stride PSF=68 f32: full 17408 B

    const int zz = blockIdx.z;
    const int h  = blockIdx.y;
    const int t0 = blockIdx.x * 64;
    const size_t qbase = ((size_t)zz * Tq + t0) * Eq + (size_t)h * Dq;
    const size_t kbase = (size_t)zz * Sq * Eq + (size_t)h * Dq;

    const int tid  = threadIdx.x;
    const int wid  = tid >> 5;
    const int lane = tid & 31;
    const int gid  = lane >> 2;
    const int t4   = lane & 3;
    const int wrow = wid * 16;

    // ---- Stage Q tile [64 rows x 64 d] bf16 ----
    #pragma unroll
    for (int i = 0; i < 4; i++) {
        int idx = tid + i * 128;
        int row = idx >> 3;
        int c8  = idx & 7;              // 8 bf16 per uint4
        uint4 v = *(const uint4*)&qi[qbase + (size_t)row * Eq + c8 * 8];
        *(uint2*)&Qs[row * QSB + c8 * 8]     = make_uint2(v.x, v.y);
        *(uint2*)&Qs[row * QSB + c8 * 8 + 4] = make_uint2(v.z, v.w);
    }
    __syncthreads();

    // ---- Q fragments (bf16 m16n8k16 A): Aq[kk][4], kk = 16-d chunks ----
    uint32_t Aq[4][4];
    #pragma unroll
    for (int kk = 0; kk < 4; kk++) {
        int r = wrow + gid;
        int c = kk * 16 + 2 * t4;
        Aq[kk][0] = *(const uint32_t*)&Qs[r * QSB + c];
        Aq[kk][1] = *(const uint32_t*)&Qs[(r + 8) * QSB + c];
        Aq[kk][2] = *(const uint32_t*)&Qs[r * QSB + c + 8];
        Aq[kk][3] = *(const uint32_t*)&Qs[(r + 8) * QSB + c + 8];
    }

    float out[8][4];
    #pragma unroll
    for (int j = 0; j < 8; j++)
        #pragma unroll
        for (int c = 0; c < 4; c++) out[j][c] = 0.f;
    float mrow[2] = {-1e30f, -1e30f};
    float lrow[2] = {0.f, 0.f};
    const float kappa = 0.125f * 1.44269504088896340736f;

    for (int s0 = 0; s0 < Sq; s0 += 64) {
        __syncthreads();
        // K chunk [64 keys x 64 d] bf16
        #pragma unroll
        for (int i = 0; i < 4; i++) {
            int idx = tid + i * 128;
            int row = idx >> 3;
            int c8  = idx & 7;
            uint4 v = *(const uint4*)&ki[kbase + (size_t)(s0 + row) * Eq + c8 * 8];
            *(uint2*)&Ks[row * KSB + c8 * 8]     = make_uint2(v.x, v.y);
            *(uint2*)&Ks[row * KSB + c8 * 8 + 4] = make_uint2(v.z, v.w);
        }
        // V chunk [64 keys x 64 d] f32 (tf32-rounded)
        #pragma unroll
        for (int i = 0; i < 8; i++) {
            int idx = tid + i * 128;
            int row = idx >> 4;
            int c4  = idx & 15;
            float4 vv = *(const float4*)&vi[kbase + (size_t)(s0 + row) * Eq + c4 * 4];
            *(float4*)&Vs[row * VSF + c4 * 4] = f2tf32_4(vv);
        }
        __syncthreads();

        // ---- Scores S[16 x 64] per warp (bf16 MMA) ----
        float sc[8][4];
        #pragma unroll
        for (int j = 0; j < 8; j++)
            #pragma unroll
            for (int c = 0; c < 4; c++) sc[j][c] = 0.f;
        #pragma unroll
        for (int kk = 0; kk < 4; kk++) {
            #pragma unroll
            for (int j = 0; j < 8; j++) {
                const __nv_bfloat16* kr = &Ks[(j * 8 + gid) * KSB + kk * 16 + 2 * t4];
                uint32_t b[2];
                b[0] = *(const uint32_t*)kr;
                b[1] = *(const uint32_t*)(kr + 8);
                mma_bf16(sc[j], Aq[kk], b);
            }
        }

        #pragma unroll
        for (int j = 0; j < 8; j++)
            #pragma unroll
            for (int c = 0; c < 4; c++) sc[j][c] *= kappa;

        // ---- Online softmax (log2 domain), exp in place ----
        #pragma unroll
        for (int r = 0; r < 2; r++) {
            float mx = -1e30f;
            #pragma unroll
            for (int j = 0; j < 8; j++)
                mx = fmaxf(mx, fmaxf(sc[j][2*r], sc[j][2*r + 1]));
            mx = fmaxf(mx, __shfl_xor_sync(0xffffffffu, mx, 1));
            mx = fmaxf(mx, __shfl_xor_sync(0xffffffffu, mx, 2));
            float mn = fmaxf(mrow[r], mx);
            float corr = exp2f(mrow[r] - mn);
            mrow[r] = mn;
            float rs = 0.f;
            #pragma unroll
            for (int j = 0; j < 8; j++) {
                float p0 = exp2f(sc[j][2*r]     - mn);
                float p1 = exp2f(sc[j][2*r + 1] - mn);
                sc[j][2*r]     = p0;
                sc[j][2*r + 1] = p1;
                rs += p0 + p1;
            }
            rs += __shfl_xor_sync(0xffffffffu, rs, 1);
            rs += __shfl_xor_sync(0xffffffffu, rs, 2);
            lrow[r] = lrow[r] * corr + rs;
            #pragma unroll
            for (int j = 0; j < 8; j++) {
                out[j][2*r]     *= corr;
                out[j][2*r + 1] *= corr;
            }
        }

        // ---- Store P [16 x 64] tf32-f32, stride 68 (own warp rows only;
        //      aliases Q region — safe, Q is register-resident) ----
        #pragma unroll
        for (int j = 0; j < 8; j++) {
            int col = j * 8 + 2 * t4;
            *(float2*)&Ps[(wrow + gid) * PSF + col] =
                make_float2(f2tf32(sc[j][0]), f2tf32(sc[j][1]));
            *(float2*)&Ps[(wrow + gid + 8) * PSF + col] =
                make_float2(f2tf32(sc[j][2]), f2tf32(sc[j][3]));
        }
        __syncwarp();

        // ---- PV: out[16 x 64] += P[16 x 64k] * V[64k x 64d]  (tf32 MMA) ----
        #pragma unroll
        for (int kk = 0; kk < 8; kk++) {
            float afr[4];
            int r = wrow + gid;
            int c = kk * 8 + t4;
            afr[0] = Ps[r * PSF + c];
            afr[1] = Ps[(r + 8) * PSF + c];
            afr[2] = Ps[r * PSF + c + 4];
            afr[3] = Ps[(r + 8) * PSF + c + 4];
            #pragma unroll
            for (int j = 0; j < 8; j++) {
                float bfr[2];
                int key = kk * 8 + t4;
                int d   = j * 8 + gid;
                bfr[0] = Vs[key * VSF + d];
                bfr[1] = Vs[(key + 4) * VSF + d];
                mma_tf32(out[j], afr, bfr);
            }
        }
    }

    float inv0 = 1.0f / lrow[0];
    float inv1 = 1.0f / lrow[1];
    int r0 = wrow + gid;
    #pragma unroll
    for (int j = 0; j < 8; j++) {
        int col = j * 8 + 2 * t4;
        *(float2*)&ctx[qbase + (size_t)r0 * Eq + col] =
            make_float2(out[j][0] * inv0, out[j][1] * inv0);
        *(float2*)&ctx[qbase + (size_t)(r0 + 8) * Eq + col] =
            make_float2(out[j][2] * inv1, out[j][3] * inv1);
    }
}

// ---------------------------------------------------------------------------
// Launch
// ---------------------------------------------------------------------------
extern "C" void kernel_launch(void* const* d_in, const int* in_sizes, int n_in,
                              void* d_out, int out_size)
{
    const float* query = (const float*)d_in[0];
    const float* key_  = (const float*)d_in[1];
    const float* value = (const float*)d_in[2];
    const float* Wqg   = (const float*)d_in[3];
    const float* bqg   = (const float*)d_in[4];
    const float* Wk    = (const float*)d_in[5];
    const float* bk    = (const float*)d_in[6];
    const float* Wv    = (const float*)d_in[7];
    const float* bv    = (const float*)d_in[8];
    const float* Wq_in = (const float*)d_in[9];
    const float* bq_in = (const float*)d_in[10];
    const float* Wk_in = (const float*)d_in[11];
    const float* bk_in = (const float*)d_in[12];
    const float* Wv_in = (const float*)d_in[13];
    const float* bv_in = (const float*)d_in[14];
    const float* Wout  = (const float*)d_in[15];
    const float* bout  = (const float*)d_in[16];
    float* out = (float*)d_out;

    float *wc, *bc, *viP, *ctx;
    __nv_bfloat16 *qibP, *kibP;
    cudaGetSymbolAddress((void**)&wc,   g_wc);
    cudaGetSymbolAddress((void**)&bc,   g_bc);
    cudaGetSymbolAddress((void**)&qibP, g_qib);
    cudaGetSymbolAddress((void**)&kibP, g_kib);
    cudaGetSymbolAddress((void**)&viP,  g_vi);
    cudaGetSymbolAddress((void**)&ctx,  g_ctx);

    // 1) Fused bias compose
    biascomp_all<<<dim3(Eq / 8, 12), 256>>>(Wq_in, Wk_in, Wv_in,
                                            bqg, bk, bv,
                                            bq_in, bk_in, bv_in, bc);

    // 2) Fused weight compose (one launch, z = 12)
    gemm_k<0><<<dim3(Eq / 64, Eq / 128, 12), 128>>>(
        Wq_in, Wk_in, Wv_in, Wqg, Wk, Wv, wc, nullptr, nullptr);

    // 3) Fused projections: ki (bf16), vi (f32), qi (bf16)
    gemm_k<1><<<dim3(Eq / 64, (Bq * Sq) / 128, 12), 128>>>(
        query, key_, value, wc, bc, nullptr,
        (float*)kibP, viP, (float*)qibP);

    // 4) Attention (mixed bf16-QK / tf32-PV)
    flash_mixed_kernel<<<dim3(Tq / 64, Hq, Bq * Gq), 128>>>(qibP, kibP, viP, ctx);

    // 5) Output projection + scatter
    gemm_k<2><<<dim3(Eq / 64, (Bq * Tq) / 128, Gq), 128>>>(
        ctx, Wout, bout, nullptr, nullptr, nullptr, out, nullptr, nullptr);
}

// round 10
// speedup vs baseline: 1.8903x; 1.1108x over previous
#include <cuda_runtime.h>
#include <cuda_bf16.h>
#include <cstdint>

// Problem constants
#define Bq 2
#define Sq 2048
#define Eq 768
#define Hq 12
#define Gq 4
#define Dq 64
#define Tq 512   // Sq / Gq

#define EEc  ((size_t)Eq * Eq)
#define BTEc ((size_t)Bq * Tq * Eq)
#define BSEc ((size_t)Bq * Sq * Eq)

// ---------------------------------------------------------------------------
// Scratch (device globals)
// ---------------------------------------------------------------------------
__device__ float g_wc[12 * EEc];     // composed weights [q g0..3 | k g0..3 | v g0..3]
__device__ float g_bc[12 * Eq];      // composed biases
__device__ __nv_bfloat16 g_qib[(size_t)Gq*Bq*Tq*Eq];   // [g][b*T+t][f] bf16
__device__ __nv_bfloat16 g_kib[(size_t)Gq*Bq*Sq*Eq];   // [g][b*S+s][f] bf16
__device__ float g_vi [(size_t)Gq*Bq*Sq*Eq];           // [g][b*S+s][f] fp32
__device__ float g_ctx[(size_t)Gq*Bq*Tq*Eq];           // [g][b*T+t][f] fp32

// ---------------------------------------------------------------------------
// helpers
// ---------------------------------------------------------------------------
__device__ __forceinline__ float f2tf32(float x) {
    uint32_t r;
    asm("cvt.rna.tf32.f32 %0, %1;" : "=r"(r) : "f"(x));
    return __uint_as_float(r);
}
__device__ __forceinline__ float4 f2tf32_4(float4 v) {
    return make_float4(f2tf32(v.x), f2tf32(v.y), f2tf32(v.z), f2tf32(v.w));
}
__device__ __forceinline__ void mma_tf32(float (&d)[4], const float a[4], const float b[2]) {
    asm volatile(
        "mma.sync.aligned.m16n8k8.row.col.f32.tf32.tf32.f32 "
        "{%0,%1,%2,%3}, {%4,%5,%6,%7}, {%8,%9}, {%0,%1,%2,%3};\n"
        : "+f"(d[0]), "+f"(d[1]), "+f"(d[2]), "+f"(d[3])
        : "r"(__float_as_uint(a[0])), "r"(__float_as_uint(a[1])),
          "r"(__float_as_uint(a[2])), "r"(__float_as_uint(a[3])),
          "r"(__float_as_uint(b[0])), "r"(__float_as_uint(b[1])));
}
__device__ __forceinline__ void mma_bf16(float (&d)[4], const uint32_t a[4], const uint32_t b[2]) {
    asm volatile(
        "mma.sync.aligned.m16n8k16.row.col.f32.bf16.bf16.f32 "
        "{%0,%1,%2,%3}, {%4,%5,%6,%7}, {%8,%9}, {%0,%1,%2,%3};\n"
        : "+f"(d[0]), "+f"(d[1]), "+f"(d[2]), "+f"(d[3])
        : "r"(a[0]), "r"(a[1]), "r"(a[2]), "r"(a[3]),
          "r"(b[0]), "r"(b[1]));
}
__device__ __forceinline__ uint32_t packbf(float lo, float hi) {
    uint32_t r;
    asm("cvt.rn.bf16x2.f32 %0, %1, %2;" : "=r"(r) : "f"(hi), "f"(lo));
    return r;
}

// ---------------------------------------------------------------------------
// Unified tf32 GEMM, 128 thr / 4 warps, block tile 128m x 128n,
// warp tile 64x64 (mt=4, nt=8). Single-buffer smem + register prefetch.
// MODE 0: weight compose wc[z] = Win[sel][g] @ Wouter[sel]  (W read [k][n])
// MODE 1: projections: sel0 ki(bf16) = key@Wc_k ; sel1 vi(f32) = value@Wc_v ;
//                      sel2 qi(bf16) = gather_g(query)@Wc_q  (y<8)
// MODE 2: output out = scatter_g(ctx[z] @ Wout[z].T + bout[z])
// ---------------------------------------------------------------------------
#define GS 20
#define WKN 132   // MODE0 Ws [k][n] stride (n-tile 128): banks 4*t4+gid distinct

template<int MODE>
__global__ __launch_bounds__(128)
void gemm_k(const float* __restrict__ P0, const float* __restrict__ P1,
            const float* __restrict__ P2, const float* __restrict__ P3,
            const float* __restrict__ P4, const float* __restrict__ P5,
            float* __restrict__ O0, float* __restrict__ O1, float* __restrict__ O2)
{
    __shared__ float As[128 * GS];   // 2560 floats
    __shared__ float Ws[128 * GS];   // 2560 floats (covers MODE0 16*132 = 2112 too)

    const int z = blockIdx.z;
    const int sel = z >> 2, g = z & 3;

    const float* Ab; const float* Wb; const float* bb = nullptr; float* Cb = nullptr;
    bool amap = false, cmap = false, bfout = false;
    if (MODE == 0) {
        Ab = (sel == 0 ? P0 : sel == 1 ? P1 : P2) + (size_t)g * EEc;
        Wb = (sel == 0 ? P3 : sel == 1 ? P4 : P5);
        Cb = O0 + (size_t)z * EEc;
    } else if (MODE == 1) {
        if (sel == 2 && blockIdx.y >= 8) return;
        if (sel == 0)      { Ab = P1; Wb = P3 + (size_t)(4+g)*EEc; bb = P4 + (4+g)*Eq; Cb = O0; bfout = true; }
        else if (sel == 1) { Ab = P2; Wb = P3 + (size_t)(8+g)*EEc; bb = P4 + (8+g)*Eq; Cb = O1 + (size_t)g*BSEc; }
        else               { Ab = P0; Wb = P3 + (size_t)g*EEc;     bb = P4 + g*Eq;     Cb = O2; bfout = true; amap = true; }
    } else {
        Ab = P0 + (size_t)z * BTEc;
        Wb = P1 + (size_t)z * EEc;
        bb = P2 + z * Eq;
        Cb = O0; cmap = true;
    }
    __nv_bfloat16* Cb16 = nullptr;
    if (MODE == 1 && bfout) {
        Cb16 = (sel == 0) ? ((__nv_bfloat16*)O0 + (size_t)g * BSEc)
                          : ((__nv_bfloat16*)O2 + (size_t)g * BTEc);
    }

    const int m0 = blockIdx.y * 128;
    const int n0 = blockIdx.x * 128;
    const int tid  = threadIdx.x;
    const int wid  = tid >> 5;
    const int lane = tid & 31;
    const int gid  = lane >> 2;
    const int t4   = lane & 3;
    const int wm   = (wid & 1) * 64;
    const int wn   = (wid >> 1) * 64;

    float acc[4][8][4];
    #pragma unroll
    for (int a = 0; a < 4; a++)
        #pragma unroll
        for (int b = 0; b < 8; b++)
            #pragma unroll
            for (int c = 0; c < 4; c++) acc[a][b][c] = 0.f;

    float4 pa[4], pw[4];

    auto loadA = [&](int k0) {
        #pragma unroll
        for (int p = 0; p < 4; p++) {
            int idx = tid + p * 128;
            int row = m0 + (idx >> 2);
            int q = (idx & 3) * 4;
            size_t gr;
            if (amap) gr = (size_t)(row >> 9) * Sq + (size_t)(row & 511) * Gq + g;
            else      gr = (size_t)row;
            pa[p] = *(const float4*)&Ab[gr * Eq + k0 + q];
        }
    };
    auto loadW = [&](int k0) {
        if (MODE != 0) {
            #pragma unroll
            for (int p = 0; p < 4; p++) {
                int idx = tid + p * 128;
                int row = n0 + (idx >> 2);
                int q = (idx & 3) * 4;
                pw[p] = *(const float4*)&Wb[(size_t)row * Eq + k0 + q];
            }
        } else {
            #pragma unroll
            for (int p = 0; p < 4; p++) {
                int idx = tid + p * 128;
                int e  = idx >> 5;            // 0..15 (k within chunk)
                int jq = (idx & 31) * 4;      // 0..124 (n within tile)
                pw[p] = *(const float4*)&Wb[(size_t)(k0 + e) * Eq + n0 + jq];
            }
        }
    };
    auto storeT = [&]() {
        #pragma unroll
        for (int p = 0; p < 4; p++) {
            int idx = tid + p * 128;
            int row = idx >> 2;
            int q = (idx & 3) * 4;
            *(float4*)&As[row * GS + q] = f2tf32_4(pa[p]);
        }
        if (MODE != 0) {
            #pragma unroll
            for (int p = 0; p < 4; p++) {
                int idx = tid + p * 128;
                int row = idx >> 2;
                int q = (idx & 3) * 4;
                *(float4*)&Ws[row * GS + q] = f2tf32_4(pw[p]);
            }
        } else {
            #pragma unroll
            for (int p = 0; p < 4; p++) {
                int idx = tid + p * 128;
                int e  = idx >> 5;
                int jq = (idx & 31) * 4;
                *(float4*)&Ws[e * WKN + jq] = f2tf32_4(pw[p]);
            }
        }
    };

    loadA(0); loadW(0);

    for (int k0 = 0; k0 < Eq; k0 += 16) {
        storeT();
        __syncthreads();
        if (k0 + 16 < Eq) { loadA(k0 + 16); loadW(k0 + 16); }

        #pragma unroll
        for (int kk = 0; kk < 2; kk++) {
            float afr[4][4];
            #pragma unroll
            for (int mt = 0; mt < 4; mt++) {
                int r = wm + mt * 16 + gid;
                int c = kk * 8 + t4;
                afr[mt][0] = As[r * GS + c];
                afr[mt][1] = As[(r + 8) * GS + c];
                afr[mt][2] = As[r * GS + c + 4];
                afr[mt][3] = As[(r + 8) * GS + c + 4];
            }
            float bfr[8][2];
            #pragma unroll
            for (int nt = 0; nt < 8; nt++) {
                int r = wn + nt * 8 + gid;
                int c = kk * 8 + t4;
                if (MODE == 0) {
                    bfr[nt][0] = Ws[c * WKN + r];
                    bfr[nt][1] = Ws[(c + 4) * WKN + r];
                } else {
                    bfr[nt][0] = Ws[r * GS + c];
                    bfr[nt][1] = Ws[r * GS + c + 4];
                }
            }
            #pragma unroll
            for (int mt = 0; mt < 4; mt++)
                #pragma unroll
                for (int nt = 0; nt < 8; nt++)
                    mma_tf32(acc[mt][nt], afr[mt], bfr[nt]);
        }
        __syncthreads();
    }

    #pragma unroll
    for (int mt = 0; mt < 4; mt++) {
        int m  = m0 + wm + mt * 16 + gid;
        int m2 = m + 8;
        size_t r0, r1;
        if (cmap) {
            r0 = (size_t)(m  >> 9) * Sq + (size_t)(m  & 511) * Gq + g;
            r1 = (size_t)(m2 >> 9) * Sq + (size_t)(m2 & 511) * Gq + g;
        } else { r0 = (size_t)m; r1 = (size_t)m2; }
        #pragma unroll
        for (int nt = 0; nt < 8; nt++) {
            int n = n0 + wn + nt * 8 + 2 * t4;
            float b0 = 0.f, b1 = 0.f;
            if (MODE != 0) { b0 = bb[n]; b1 = bb[n + 1]; }
            if (MODE == 1 && bfout) {
                *(uint32_t*)&Cb16[r0 * Eq + n] = packbf(acc[mt][nt][0] + b0, acc[mt][nt][1] + b1);
                *(uint32_t*)&Cb16[r1 * Eq + n] = packbf(acc[mt][nt][2] + b0, acc[mt][nt][3] + b1);
            } else {
                *(float2*)&Cb[r0 * Eq + n] = make_float2(acc[mt][nt][0] + b0, acc[mt][nt][1] + b1);
                *(float2*)&Cb[r1 * Eq + n] = make_float2(acc[mt][nt][2] + b0, acc[mt][nt][3] + b1);
            }
        }
    }
}

// ---------------------------------------------------------------------------
// Fused bias compose
// ---------------------------------------------------------------------------
__global__ void biascomp_all(const float* __restrict__ Wq_in, const float* __restrict__ Wk_in,
                             const float* __restrict__ Wv_in,
                             const float* __restrict__ bqg, const float* __restrict__ bk,
                             const float* __restrict__ bv,
                             const float* __restrict__ bq_in, const float* __restrict__ bk_in,
                             const float* __restrict__ bv_in,
                             float* __restrict__ bc)
{
    int y = blockIdx.y;
    int sel = y >> 2, g = y & 3;
    const float* Win = (sel == 0 ? Wq_in : sel == 1 ? Wk_in : Wv_in) + (size_t)g * EEc;
    const float* bo  = (sel == 0 ? bqg : sel == 1 ? bk : bv);
    const float* bi  = (sel == 0 ? bq_in : sel == 1 ? bk_in : bv_in) + g * Eq;
    int f = blockIdx.x * 8 + (threadIdx.x >> 5);
    int lane = threadIdx.x & 31;
    const float* wr = Win + (size_t)f * Eq;
    float s = 0.f;
    for (int j = lane * 4; j < Eq; j += 128) {
        float4 w = *(const float4*)&wr[j];
        float4 b = *(const float4*)&bo[j];
        s += w.x*b.x + w.y*b.y + w.z*b.z + w.w*b.w;
    }
    #pragma unroll
    for (int o = 16; o; o >>= 1) s += __shfl_xor_sync(0xffffffffu, s, o);
    if (lane == 0) bc[(size_t)y * Eq + f] = s + bi[f];
}

// ---------------------------------------------------------------------------
// Flash attention, mixed precision (UNCHANGED from round 8 — proven 205 us):
//   QK: bf16 MMA; softmax fp32; P tf32-f32 stride 68; PV: tf32 MMA.
// ---------------------------------------------------------------------------
#define KSB 72   // K smem stride (bf16)
#define VSF 72   // V smem stride (f32)
#define QSB 72   // Q staging stride (bf16)
#define PSF 68   // P smem stride (f32)

__global__ __launch_bounds__(128)
void flash_mixed_kernel(const __nv_bfloat16* __restrict__ qi,
                        const __nv_bfloat16* __restrict__ ki,
                        const float* __restrict__ vi,
                        float* __restrict__ ctx)
{
    __shared__ __align__(16) __nv_bfloat16 Ks[64 * KSB];
    __shared__ __align__(16) float         Vs[64 * VSF];
    __shared__ __align__(16) unsigned char QPbuf[64 * PSF * 4];
    __nv_bfloat16* Qs = (__nv_bfloat16*)QPbuf;
    float*         Ps = (float*)QPbuf;

    const int zz = blockIdx.z;
    const int h  = blockIdx.y;
    const int t0 = blockIdx.x * 64;
    const size_t qbase = ((size_t)zz * Tq + t0) * Eq + (size_t)h * Dq;
    const size_t kbase = (size_t)zz * Sq * Eq + (size_t)h * Dq;

    const int tid  = threadIdx.x;
    const int wid  = tid >> 5;
    const int lane = tid & 31;
    const int gid  = lane >> 2;
    const int t4   = lane & 3;
    const int wrow = wid * 16;

    #pragma unroll
    for (int i = 0; i < 4; i++) {
        int idx = tid + i * 128;
        int row = idx >> 3;
        int c8  = idx & 7;
        uint4 v = *(const uint4*)&qi[qbase + (size_t)row * Eq + c8 * 8];
        *(uint2*)&Qs[row * QSB + c8 * 8]     = make_uint2(v.x, v.y);
        *(uint2*)&Qs[row * QSB + c8 * 8 + 4] = make_uint2(v.z, v.w);
    }
    __syncthreads();

    uint32_t Aq[4][4];
    #pragma unroll
    for (int kk = 0; kk < 4; kk++) {
        int r = wrow + gid;
        int c = kk * 16 + 2 * t4;
        Aq[kk][0] = *(const uint32_t*)&Qs[r * QSB + c];
        Aq[kk][1] = *(const uint32_t*)&Qs[(r + 8) * QSB + c];
        Aq[kk][2] = *(const uint32_t*)&Qs[r * QSB + c + 8];
        Aq[kk][3] = *(const uint32_t*)&Qs[(r + 8) * QSB + c + 8];
    }

    float out[8][4];
    #pragma unroll
    for (int j = 0; j < 8; j++)
        #pragma unroll
        for (int c = 0; c < 4; c++) out[j][c] = 0.f;
    float mrow[2] = {-1e30f, -1e30f};
    float lrow[2] = {0.f, 0.f};
    const float kappa = 0.125f * 1.44269504088896340736f;

    for (int s0 = 0; s0 < Sq; s0 += 64) {
        __syncthreads();
        #pragma unroll
        for (int i = 0; i < 4; i++) {
            int idx = tid + i * 128;
            int row = idx >> 3;
            int c8  = idx & 7;
            uint4 v = *(const uint4*)&ki[kbase + (size_t)(s0 + row) * Eq + c8 * 8];
            *(uint2*)&Ks[row * KSB + c8 * 8]     = make_uint2(v.x, v.y);
            *(uint2*)&Ks[row * KSB + c8 * 8 + 4] = make_uint2(v.z, v.w);
        }
        #pragma unroll
        for (int i = 0; i < 8; i++) {
            int idx = tid + i * 128;
            int row = idx >> 4;
            int c4  = idx & 15;
            float4 vv = *(const float4*)&vi[kbase + (size_t)(s0 + row) * Eq + c4 * 4];
            *(float4*)&Vs[row * VSF + c4 * 4] = f2tf32_4(vv);
        }
        __syncthreads();

        float sc[8][4];
        #pragma unroll
        for (int j = 0; j < 8; j++)
            #pragma unroll
            for (int c = 0; c < 4; c++) sc[j][c] = 0.f;
        #pragma unroll
        for (int kk = 0; kk < 4; kk++) {
            #pragma unroll
            for (int j = 0; j < 8; j++) {
                const __nv_bfloat16* kr = &Ks[(j * 8 + gid) * KSB + kk * 16 + 2 * t4];
                uint32_t b[2];
                b[0] = *(const uint32_t*)kr;
                b[1] = *(const uint32_t*)(kr + 8);
                mma_bf16(sc[j], Aq[kk], b);
            }
        }

        #pragma unroll
        for (int j = 0; j < 8; j++)
            #pragma unroll
            for (int c = 0; c < 4; c++) sc[j][c] *= kappa;

        #pragma unroll
        for (int r = 0; r < 2; r++) {
            float mx = -1e30f;
            #pragma unroll
            for (int j = 0; j < 8; j++)
                mx = fmaxf(mx, fmaxf(sc[j][2*r], sc[j][2*r + 1]));
            mx = fmaxf(mx, __shfl_xor_sync(0xffffffffu, mx, 1));
            mx = fmaxf(mx, __shfl_xor_sync(0xffffffffu, mx, 2));
            float mn = fmaxf(mrow[r], mx);
            float corr = exp2f(mrow[r] - mn);
            mrow[r] = mn;
            float rs = 0.f;
            #pragma unroll
            for (int j = 0; j < 8; j++) {
                float p0 = exp2f(sc[j][2*r]     - mn);
                float p1 = exp2f(sc[j][2*r + 1] - mn);
                sc[j][2*r]     = p0;
                sc[j][2*r + 1] = p1;
                rs += p0 + p1;
            }
            rs += __shfl_xor_sync(0xffffffffu, rs, 1);
            rs += __shfl_xor_sync(0xffffffffu, rs, 2);
            lrow[r] = lrow[r] * corr + rs;
            #pragma unroll
            for (int j = 0; j < 8; j++) {
                out[j][2*r]     *= corr;
                out[j][2*r + 1] *= corr;
            }
        }

        #pragma unroll
        for (int j = 0; j < 8; j++) {
            int col = j * 8 + 2 * t4;
            *(float2*)&Ps[(wrow + gid) * PSF + col] =
                make_float2(f2tf32(sc[j][0]), f2tf32(sc[j][1]));
            *(float2*)&Ps[(wrow + gid + 8) * PSF + col] =
                make_float2(f2tf32(sc[j][2]), f2tf32(sc[j][3]));
        }
        __syncwarp();

        #pragma unroll
        for (int kk = 0; kk < 8; kk++) {
            float afr[4];
            int r = wrow + gid;
            int c = kk * 8 + t4;
            afr[0] = Ps[r * PSF + c];
            afr[1] = Ps[(r + 8) * PSF + c];
            afr[2] = Ps[r * PSF + c + 4];
            afr[3] = Ps[(r + 8) * PSF + c + 4];
            #pragma unroll
            for (int j = 0; j < 8; j++) {
                float bfr[2];
                int key = kk * 8 + t4;
                int d   = j * 8 + gid;
                bfr[0] = Vs[key * VSF + d];
                bfr[1] = Vs[(key + 4) * VSF + d];
                mma_tf32(out[j], afr, bfr);
            }
        }
    }

    float inv0 = 1.0f / lrow[0];
    float inv1 = 1.0f / lrow[1];
    int r0 = wrow + gid;
    #pragma unroll
    for (int j = 0; j < 8; j++) {
        int col = j * 8 + 2 * t4;
        *(float2*)&ctx[qbase + (size_t)r0 * Eq + col] =
            make_float2(out[j][0] * inv0, out[j][1] * inv0);
        *(float2*)&ctx[qbase + (size_t)(r0 + 8) * Eq + col] =
            make_float2(out[j][2] * inv1, out[j][3] * inv1);
    }
}

// ---------------------------------------------------------------------------
// Launch
// ---------------------------------------------------------------------------
extern "C" void kernel_launch(void* const* d_in, const int* in_sizes, int n_in,
                              void* d_out, int out_size)
{
    const float* query = (const float*)d_in[0];
    const float* key_  = (const float*)d_in[1];
    const float* value = (const float*)d_in[2];
    const float* Wqg   = (const float*)d_in[3];
    const float* bqg   = (const float*)d_in[4];
    const float* Wk    = (const float*)d_in[5];
    const float* bk    = (const float*)d_in[6];
    const float* Wv    = (const float*)d_in[7];
    const float* bv    = (const float*)d_in[8];
    const float* Wq_in = (const float*)d_in[9];
    const float* bq_in = (const float*)d_in[10];
    const float* Wk_in = (const float*)d_in[11];
    const float* bk_in = (const float*)d_in[12];
    const float* Wv_in = (const float*)d_in[13];
    const float* bv_in = (const float*)d_in[14];
    const float* Wout  = (const float*)d_in[15];
    const float* bout  = (const float*)d_in[16];
    float* out = (float*)d_out;

    float *wc, *bc, *viP, *ctx;
    __nv_bfloat16 *qibP, *kibP;
    cudaGetSymbolAddress((void**)&wc,   g_wc);
    cudaGetSymbolAddress((void**)&bc,   g_bc);
    cudaGetSymbolAddress((void**)&qibP, g_qib);
    cudaGetSymbolAddress((void**)&kibP, g_kib);
    cudaGetSymbolAddress((void**)&viP,  g_vi);
    cudaGetSymbolAddress((void**)&ctx,  g_ctx);

    // 1) Fused bias compose
    biascomp_all<<<dim3(Eq / 8, 12), 256>>>(Wq_in, Wk_in, Wv_in,
                                            bqg, bk, bv,
                                            bq_in, bk_in, bv_in, bc);

    // 2) Fused weight compose (one launch, z = 12), 128x128 tiles
    gemm_k<0><<<dim3(Eq / 128, Eq / 128, 12), 128>>>(
        Wq_in, Wk_in, Wv_in, Wqg, Wk, Wv, wc, nullptr, nullptr);

    // 3) Fused projections: ki (bf16), vi (f32), qi (bf16), 128x128 tiles
    gemm_k<1><<<dim3(Eq / 128, (Bq * Sq) / 128, 12), 128>>>(
        query, key_, value, wc, bc, nullptr,
        (float*)kibP, viP, (float*)qibP);

    // 4) Attention (mixed bf16-QK / tf32-PV)
    flash_mixed_kernel<<<dim3(Tq / 64, Hq, Bq * Gq), 128>>>(qibP, kibP, viP, ctx);

    // 5) Output projection + scatter, 128x128 tiles
    gemm_k<2><<<dim3(Eq / 128, (Bq * Tq) / 128, Gq), 128>>>(
        ctx, Wout, bout, nullptr, nullptr, nullptr, out, nullptr, nullptr);
}